// round 1
// baseline (speedup 1.0000x reference)
#include <cuda_runtime.h>

// Problem constants
#define B_TOTAL   65536
#define IN_DIM    1260
#define HDIM      40        // hidden size
#define NREAL     120       // packed gate cols: i(40) g(40) o(40); f gate dropped (c0 == 0)
#define NCOL      128       // padded gate cols for alignment
#define TILE_B    64
#define KT        36        // 1260 = 35 * 36
#define NTHREADS  256
#define XS_STRIDE 37

// Packed/transposed layer-0 weight: g_Wt[k][j] = W_ih0[colmap(j)][k], j<120; 0 otherwise.
// colmap(j) = j < 40 ? j : j + 40   (skip f rows 40..79)
__device__ float g_Wt[IN_DIM * NCOL];

__global__ void prep_kernel(const float* __restrict__ W_ih0) {
    int idx = blockIdx.x * blockDim.x + threadIdx.x;
    if (idx >= IN_DIM * NCOL) return;
    int k = idx / NCOL;
    int j = idx - k * NCOL;
    float v = 0.0f;
    if (j < NREAL) {
        int r = (j < HDIM) ? j : j + HDIM;
        v = W_ih0[r * IN_DIM + k];
    }
    g_Wt[idx] = v;
}

__device__ __forceinline__ float sigmoidf_(float v) {
    return 1.0f / (1.0f + __expf(-v));
}

__device__ __forceinline__ unsigned long long pack2(float lo, float hi) {
    unsigned long long r;
    asm("mov.b64 %0, {%1, %2};" : "=l"(r) : "f"(lo), "f"(hi));
    return r;
}
__device__ __forceinline__ void unpack2(unsigned long long v, float& lo, float& hi) {
    asm("mov.b64 {%0, %1}, %2;" : "=f"(lo), "=f"(hi) : "l"(v));
}
// Packed dual-FMA (Blackwell f32x2 pipe): d = a * b + d elementwise on 2 packed floats
__device__ __forceinline__ void fma2(unsigned long long& d, unsigned long long a, unsigned long long b) {
    asm("fma.rn.f32x2 %0, %1, %2, %0;" : "+l"(d) : "l"(a), "l"(b));
}

// Small LSTM layer (K = 40), h_in/h_out in smem, weights from global (L2-resident).
// Computes only i, g, o gates; c0 == 0 so c = sigmoid(i)*tanh(g), h = sigmoid(o)*tanh(c).
__device__ __forceinline__ void small_lstm_layer(
    const float* __restrict__ hin, float* __restrict__ hout,
    const float* __restrict__ W, const float* __restrict__ bi,
    const float* __restrict__ bh, int tid)
{
    #pragma unroll
    for (int l = 0; l < (TILE_B * HDIM) / NTHREADS; l++) {
        int idx = tid + l * NTHREADS;       // < 2560
        int r = idx / HDIM;
        int n = idx - r * HDIM;
        float si = bi[n] + bh[n];                               // i gate row n
        float sg = bi[2 * HDIM + n] + bh[2 * HDIM + n];         // g gate row 80+n
        float so = bi[3 * HDIM + n] + bh[3 * HDIM + n];         // o gate row 120+n
        const float4* hv = reinterpret_cast<const float4*>(&hin[r * HDIM]);
        const float4* wi = reinterpret_cast<const float4*>(&W[n * HDIM]);
        const float4* wg = reinterpret_cast<const float4*>(&W[(2 * HDIM + n) * HDIM]);
        const float4* wo = reinterpret_cast<const float4*>(&W[(3 * HDIM + n) * HDIM]);
        #pragma unroll
        for (int q = 0; q < HDIM / 4; q++) {
            float4 h4 = hv[q];
            float4 a = wi[q];
            float4 b = wg[q];
            float4 c = wo[q];
            si += h4.x * a.x + h4.y * a.y + h4.z * a.z + h4.w * a.w;
            sg += h4.x * b.x + h4.y * b.y + h4.z * b.z + h4.w * b.w;
            so += h4.x * c.x + h4.y * c.y + h4.z * c.z + h4.w * c.w;
        }
        float cc = sigmoidf_(si) * tanhf(sg);
        hout[r * HDIM + n] = sigmoidf_(so) * tanhf(cc);
    }
}

__global__ __launch_bounds__(NTHREADS) void lstm_kernel(
    const float* __restrict__ x,
    const float* __restrict__ b_ih0, const float* __restrict__ b_hh0,
    const float* __restrict__ W1, const float* __restrict__ b_ih1, const float* __restrict__ b_hh1,
    const float* __restrict__ W2, const float* __restrict__ b_ih2, const float* __restrict__ b_hh2,
    const float* __restrict__ Wout, const float* __restrict__ b_out,
    float* __restrict__ out)
{
    // 43 KB static smem, phase-aliased:
    //   GEMM phase : Xs[64][37] (2368) | Ws[36][128] (4608)
    //   epilogue   : Gs[64][128] (8192) | hA[64][40] (2560)
    __shared__ float smem[TILE_B * NCOL + TILE_B * HDIM];
    float* Xs = smem;
    float* Ws = smem + TILE_B * XS_STRIDE;

    const int tid = threadIdx.x;
    const int tx = tid & 15;            // 16 col-groups of 8 cols
    const int ty = tid >> 4;            // 16 row-groups of 4 rows
    const int r0 = ty * 4;
    const int c0 = tx * 8;
    const long long bbase = (long long)blockIdx.x * TILE_B;

    // Accumulators: 4 rows x 4 packed col-pairs (8 cols), init with gate bias
    unsigned long long acc[4][4];
    {
        float bias[8];
        #pragma unroll
        for (int jj = 0; jj < 8; jj++) {
            int j = c0 + jj;
            float bv = 0.0f;
            if (j < NREAL) {
                int r = (j < HDIM) ? j : j + HDIM;
                bv = b_ih0[r] + b_hh0[r];
            }
            bias[jj] = bv;
        }
        #pragma unroll
        for (int q = 0; q < 4; q++) {
            unsigned long long p = pack2(bias[2 * q], bias[2 * q + 1]);
            #pragma unroll
            for (int i = 0; i < 4; i++) acc[i][q] = p;
        }
    }

    const float* xblk = x + bbase * IN_DIM;

    for (int kt = 0; kt < IN_DIM; kt += KT) {
        // Load X tile: 64 rows x 36 k  (coalesced along k)
        #pragma unroll
        for (int l = 0; l < (TILE_B * KT) / NTHREADS; l++) {
            int idx = tid + l * NTHREADS;           // < 2304
            int row = idx / KT;
            int kk = idx - row * KT;
            Xs[row * XS_STRIDE + kk] = xblk[row * IN_DIM + kt + kk];
        }
        // Load W tile: 36 k x 128 cols, contiguous from pre-packed g_Wt (coalesced, conflict-free)
        #pragma unroll
        for (int l = 0; l < (KT * NCOL) / NTHREADS; l++) {
            int idx = tid + l * NTHREADS;           // < 4608
            Ws[idx] = g_Wt[kt * NCOL + idx];
        }
        __syncthreads();

        #pragma unroll 4
        for (int kk = 0; kk < KT; kk++) {
            // 8 cols of W as 4 packed f32x2 pairs (two LDS.128)
            ulonglong2 bA = *reinterpret_cast<const ulonglong2*>(&Ws[kk * NCOL + c0]);
            ulonglong2 bB = *reinterpret_cast<const ulonglong2*>(&Ws[kk * NCOL + c0 + 4]);
            #pragma unroll
            for (int i = 0; i < 4; i++) {
                float av = Xs[(r0 + i) * XS_STRIDE + kk];   // broadcast across tx
                unsigned long long a2 = pack2(av, av);
                fma2(acc[i][0], a2, bA.x);
                fma2(acc[i][1], a2, bA.y);
                fma2(acc[i][2], a2, bB.x);
                fma2(acc[i][3], a2, bB.y);
            }
        }
        __syncthreads();
    }

    // ---- epilogue: activations + layers 1/2 + output head, all in smem ----
    float* Gs = smem;                       // [64][128] gate pre-activations
    float* hA = smem + TILE_B * NCOL;       // [64][40]

    #pragma unroll
    for (int i = 0; i < 4; i++) {
        float v[8];
        #pragma unroll
        for (int q = 0; q < 4; q++) unpack2(acc[i][q], v[2 * q], v[2 * q + 1]);
        float4* dst = reinterpret_cast<float4*>(&Gs[(r0 + i) * NCOL + c0]);
        dst[0] = make_float4(v[0], v[1], v[2], v[3]);
        dst[1] = make_float4(v[4], v[5], v[6], v[7]);
    }
    __syncthreads();

    // h1 = layer-0 activations
    #pragma unroll
    for (int l = 0; l < (TILE_B * HDIM) / NTHREADS; l++) {
        int idx = tid + l * NTHREADS;       // < 2560
        int r = idx / HDIM;
        int n = idx - r * HDIM;
        float gi = Gs[r * NCOL + n];
        float gg = Gs[r * NCOL + HDIM + n];
        float go = Gs[r * NCOL + 2 * HDIM + n];
        float cc = sigmoidf_(gi) * tanhf(gg);
        hA[r * HDIM + n] = sigmoidf_(go) * tanhf(cc);
    }
    __syncthreads();

    // layer 1: hA -> hB (reuse Gs region)
    float* hB = smem;                       // first 2560 floats of Gs region
    small_lstm_layer(hA, hB, W1, b_ih1, b_hh1, tid);
    __syncthreads();

    // layer 2: hB -> hA
    small_lstm_layer(hB, hA, W2, b_ih2, b_hh2, tid);
    __syncthreads();

    // output head: 64 rows x 4 outputs == 256 threads, one output each
    {
        int r = tid >> 2;
        int o = tid & 3;
        const float4* hv = reinterpret_cast<const float4*>(&hA[r * HDIM]);
        const float4* wv = reinterpret_cast<const float4*>(&Wout[o * HDIM]);
        float s = b_out[o];
        #pragma unroll
        for (int q = 0; q < HDIM / 4; q++) {
            float4 h4 = hv[q];
            float4 w4 = wv[q];
            s += h4.x * w4.x + h4.y * w4.y + h4.z * w4.z + h4.w * w4.w;
        }
        out[(bbase + r) * 4 + o] = s;
    }
}

extern "C" void kernel_launch(void* const* d_in, const int* in_sizes, int n_in,
                              void* d_out, int out_size) {
    // metadata order: x, W_ih0, W_hh0, b_ih0, b_hh0, W_ih1, W_hh1, b_ih1, b_hh1,
    //                 W_ih2, W_hh2, b_ih2, b_hh2, W_out, b_out
    const float* x     = (const float*)d_in[0];
    const float* W_ih0 = (const float*)d_in[1];
    const float* b_ih0 = (const float*)d_in[3];
    const float* b_hh0 = (const float*)d_in[4];
    const float* W_ih1 = (const float*)d_in[5];
    const float* b_ih1 = (const float*)d_in[7];
    const float* b_hh1 = (const float*)d_in[8];
    const float* W_ih2 = (const float*)d_in[9];
    const float* b_ih2 = (const float*)d_in[11];
    const float* b_hh2 = (const float*)d_in[12];
    const float* W_out = (const float*)d_in[13];
    const float* b_out = (const float*)d_in[14];
    float* out = (float*)d_out;

    prep_kernel<<<(IN_DIM * NCOL + 255) / 256, 256>>>(W_ih0);
    lstm_kernel<<<B_TOTAL / TILE_B, NTHREADS>>>(
        x, b_ih0, b_hh0,
        W_ih1, b_ih1, b_hh1,
        W_ih2, b_ih2, b_hh2,
        W_out, b_out, out);
}

// round 2
// speedup vs baseline: 1.3583x; 1.3583x over previous
#include <cuda_runtime.h>

// Problem constants
#define B_TOTAL   65536
#define IN_DIM    1260
#define HDIM      40
#define NREAL     120       // packed gate cols: i(40) g(40) o(40); f gate dropped (c0 == 0)
#define NCOL      128
#define TILE_B    128
#define KT        36        // 1260 = 35 * 36
#define NTHREADS  256
#define XS_STRIDE 40        // padded to multiple of 4 for float4 stores

// Packed/transposed layer-0 weight: g_Wt[k][j] = W_ih0[colmap(j)][k], j<120; 0 otherwise.
// colmap(j) = j < 40 ? j : j + 40   (skip f rows 40..79)
__device__ float g_Wt[IN_DIM * NCOL];

__global__ void prep_kernel(const float* __restrict__ W_ih0) {
    int idx = blockIdx.x * blockDim.x + threadIdx.x;
    if (idx >= IN_DIM * NCOL) return;
    int k = idx / NCOL;
    int j = idx - k * NCOL;
    float v = 0.0f;
    if (j < NREAL) {
        int r = (j < HDIM) ? j : j + HDIM;
        v = W_ih0[r * IN_DIM + k];
    }
    g_Wt[idx] = v;
}

__device__ __forceinline__ float sigmoidf_(float v) {
    return 1.0f / (1.0f + __expf(-v));
}

__device__ __forceinline__ unsigned long long pack2(float lo, float hi) {
    unsigned long long r;
    asm("mov.b64 %0, {%1, %2};" : "=l"(r) : "f"(lo), "f"(hi));
    return r;
}
__device__ __forceinline__ void unpack2(unsigned long long v, float& lo, float& hi) {
    asm("mov.b64 {%0, %1}, %2;" : "=f"(lo), "=f"(hi) : "l"(v));
}
// Packed dual-FMA (Blackwell f32x2): d = a * b + d elementwise on 2 packed floats
__device__ __forceinline__ void fma2(unsigned long long& d, unsigned long long a, unsigned long long b) {
    asm("fma.rn.f32x2 %0, %1, %2, %0;" : "+l"(d) : "l"(a), "l"(b));
}

// Small LSTM layer (K = 40), n-major thread map: all lanes in a warp share the
// same weight row (uniform LDG), hin rows are lane-consecutive in smem.
// Only i, g, o gates needed (c0 == 0): c = sig(i)*tanh(g), h = sig(o)*tanh(c).
__device__ __forceinline__ void small_lstm_layer(
    const float* __restrict__ hin, float* __restrict__ hout,
    const float* __restrict__ W, const float* __restrict__ bi,
    const float* __restrict__ bh, int tid)
{
    #pragma unroll
    for (int l = 0; l < (TILE_B * HDIM) / NTHREADS; l++) {
        int idx = tid + l * NTHREADS;       // < 5120
        int n = idx / TILE_B;               // uniform across warp
        int r = idx - n * TILE_B;           // lane-consecutive
        float si = bi[n] + bh[n];
        float sg = bi[2 * HDIM + n] + bh[2 * HDIM + n];
        float so = bi[3 * HDIM + n] + bh[3 * HDIM + n];
        const float4* hv = reinterpret_cast<const float4*>(&hin[r * HDIM]);
        const float4* wi = reinterpret_cast<const float4*>(&W[n * HDIM]);
        const float4* wg = reinterpret_cast<const float4*>(&W[(2 * HDIM + n) * HDIM]);
        const float4* wo = reinterpret_cast<const float4*>(&W[(3 * HDIM + n) * HDIM]);
        #pragma unroll
        for (int q = 0; q < HDIM / 4; q++) {
            float4 h4 = hv[q];
            float4 a = wi[q];
            float4 b = wg[q];
            float4 c = wo[q];
            si += h4.x * a.x + h4.y * a.y + h4.z * a.z + h4.w * a.w;
            sg += h4.x * b.x + h4.y * b.y + h4.z * b.z + h4.w * b.w;
            so += h4.x * c.x + h4.y * c.y + h4.z * c.z + h4.w * c.w;
        }
        float cc = sigmoidf_(si) * tanhf(sg);
        hout[r * HDIM + n] = sigmoidf_(so) * tanhf(cc);
    }
}

__global__ __launch_bounds__(NTHREADS, 2) void lstm_kernel(
    const float* __restrict__ x,
    const float* __restrict__ b_ih0, const float* __restrict__ b_hh0,
    const float* __restrict__ W1, const float* __restrict__ b_ih1, const float* __restrict__ b_hh1,
    const float* __restrict__ W2, const float* __restrict__ b_ih2, const float* __restrict__ b_hh2,
    const float* __restrict__ Wout, const float* __restrict__ b_out,
    float* __restrict__ out)
{
    // 64 KB dynamic smem, phase-aliased:
    //   GEMM    : Xs[128][40] (20480B) | Ws[36][128] (18432B)
    //   gates   : Gs[128][128] (65536B)
    //   layers  : hA[128][40] (20480B) | hB[128][40] (20480B)
    extern __shared__ float smem[];
    float* Xs = smem;
    float* Ws = smem + TILE_B * XS_STRIDE;

    const int tid = threadIdx.x;
    const int tx = tid & 15;            // 16 col-groups of 8 cols
    const int ty = tid >> 4;            // 16 row-groups; rows = ty + 16*i
    const int c0 = tx * 8;
    const long long bbase = (long long)blockIdx.x * TILE_B;

    // Accumulators: 8 rows x 4 packed col-pairs, init with gate bias
    unsigned long long acc[8][4];
    {
        float bias[8];
        #pragma unroll
        for (int jj = 0; jj < 8; jj++) {
            int j = c0 + jj;
            float bv = 0.0f;
            if (j < NREAL) {
                int r = (j < HDIM) ? j : j + HDIM;
                bv = b_ih0[r] + b_hh0[r];
            }
            bias[jj] = bv;
        }
        #pragma unroll
        for (int q = 0; q < 4; q++) {
            unsigned long long p = pack2(bias[2 * q], bias[2 * q + 1]);
            #pragma unroll
            for (int i = 0; i < 8; i++) acc[i][q] = p;
        }
    }

    const float* xblk = x + bbase * IN_DIM;

    for (int kt = 0; kt < IN_DIM; kt += KT) {
        // X tile: 128 rows x 36 k, float4 loads (kt % 4 == 0, row stride 1260 % 4 == 0)
        #pragma unroll
        for (int l = 0; l < 5; l++) {
            int idx = tid + l * NTHREADS;           // need < 1152
            if (idx < (TILE_B * KT) / 4) {
                int row = idx / (KT / 4);
                int q = idx - row * (KT / 4);
                float4 v = *reinterpret_cast<const float4*>(&xblk[row * IN_DIM + kt + 4 * q]);
                *reinterpret_cast<float4*>(&Xs[row * XS_STRIDE + 4 * q]) = v;
            }
        }
        // W tile: 36 k x 128 cols, contiguous float4 copy from pre-packed g_Wt
        #pragma unroll
        for (int l = 0; l < 5; l++) {
            int idx = tid + l * NTHREADS;           // need < 1152
            if (idx < (KT * NCOL) / 4) {
                float4 v = *reinterpret_cast<const float4*>(&g_Wt[kt * NCOL + 4 * idx]);
                *reinterpret_cast<float4*>(&Ws[4 * idx]) = v;
            }
        }
        __syncthreads();

        #pragma unroll 4
        for (int kk = 0; kk < KT; kk++) {
            ulonglong2 w0 = *reinterpret_cast<const ulonglong2*>(&Ws[kk * NCOL + c0]);
            ulonglong2 w1 = *reinterpret_cast<const ulonglong2*>(&Ws[kk * NCOL + c0 + 4]);
            #pragma unroll
            for (int i = 0; i < 8; i++) {
                float av = Xs[(ty + 16 * i) * XS_STRIDE + kk];   // broadcast across tx
                unsigned long long a2 = pack2(av, av);
                fma2(acc[i][0], a2, w0.x);
                fma2(acc[i][1], a2, w0.y);
                fma2(acc[i][2], a2, w1.x);
                fma2(acc[i][3], a2, w1.y);
            }
        }
        __syncthreads();
    }

    // ---- epilogue ----
    float* Gs = smem;                       // [128][128] gate pre-activations

    #pragma unroll
    for (int i = 0; i < 8; i++) {
        int r = ty + 16 * i;
        float v[8];
        #pragma unroll
        for (int q = 0; q < 4; q++) unpack2(acc[i][q], v[2 * q], v[2 * q + 1]);
        float4* dst = reinterpret_cast<float4*>(&Gs[r * NCOL + c0]);
        dst[0] = make_float4(v[0], v[1], v[2], v[3]);
        dst[1] = make_float4(v[4], v[5], v[6], v[7]);
    }
    __syncthreads();

    // h1 activations: read gates (n-fast map, conflict-free), hold in regs
    float hreg[(TILE_B * HDIM) / NTHREADS];
    #pragma unroll
    for (int l = 0; l < (TILE_B * HDIM) / NTHREADS; l++) {
        int idx = tid + l * NTHREADS;       // < 5120
        int r = idx / HDIM;
        int n = idx - r * HDIM;
        float gi = Gs[r * NCOL + n];
        float gg = Gs[r * NCOL + HDIM + n];
        float go = Gs[r * NCOL + 2 * HDIM + n];
        float cc = sigmoidf_(gi) * tanhf(gg);
        hreg[l] = sigmoidf_(go) * tanhf(cc);
    }
    __syncthreads();

    float* hA = smem;                             // [128][40]
    float* hB = smem + TILE_B * HDIM;             // [128][40]
    #pragma unroll
    for (int l = 0; l < (TILE_B * HDIM) / NTHREADS; l++) {
        int idx = tid + l * NTHREADS;
        hA[idx] = hreg[l];
    }
    __syncthreads();

    small_lstm_layer(hA, hB, W1, b_ih1, b_hh1, tid);
    __syncthreads();
    small_lstm_layer(hB, hA, W2, b_ih2, b_hh2, tid);
    __syncthreads();

    // output head: 128 rows x 4 outputs, o uniform per warp
    #pragma unroll
    for (int l = 0; l < (TILE_B * 4) / NTHREADS; l++) {
        int idx = tid + l * NTHREADS;       // < 512
        int o = idx / TILE_B;               // uniform across warp
        int r = idx - o * TILE_B;           // lane-consecutive
        const float4* hv = reinterpret_cast<const float4*>(&hA[r * HDIM]);
        const float4* wv = reinterpret_cast<const float4*>(&Wout[o * HDIM]);
        float s = b_out[o];
        #pragma unroll
        for (int q = 0; q < HDIM / 4; q++) {
            float4 h4 = hv[q];
            float4 w4 = wv[q];
            s += h4.x * w4.x + h4.y * w4.y + h4.z * w4.z + h4.w * w4.w;
        }
        out[(bbase + r) * 4 + o] = s;
    }
}

extern "C" void kernel_launch(void* const* d_in, const int* in_sizes, int n_in,
                              void* d_out, int out_size) {
    const float* x     = (const float*)d_in[0];
    const float* W_ih0 = (const float*)d_in[1];
    const float* b_ih0 = (const float*)d_in[3];
    const float* b_hh0 = (const float*)d_in[4];
    const float* W_ih1 = (const float*)d_in[5];
    const float* b_ih1 = (const float*)d_in[7];
    const float* b_hh1 = (const float*)d_in[8];
    const float* W_ih2 = (const float*)d_in[9];
    const float* b_ih2 = (const float*)d_in[11];
    const float* b_hh2 = (const float*)d_in[12];
    const float* W_out = (const float*)d_in[13];
    const float* b_out = (const float*)d_in[14];
    float* out = (float*)d_out;

    static int attr_set = 0;
    if (!attr_set) {
        cudaFuncSetAttribute(lstm_kernel,
                             cudaFuncAttributeMaxDynamicSharedMemorySize, 65536);
        attr_set = 1;
    }

    prep_kernel<<<(IN_DIM * NCOL + 255) / 256, 256>>>(W_ih0);
    lstm_kernel<<<B_TOTAL / TILE_B, NTHREADS, 65536>>>(
        x, b_ih0, b_hh0,
        W_ih1, b_ih1, b_hh1,
        W_ih2, b_ih2, b_hh2,
        W_out, b_out, out);
}

// round 3
// speedup vs baseline: 1.5792x; 1.1627x over previous
#include <cuda_runtime.h>
#include <cstdint>

// Problem constants
#define B_TOTAL   65536
#define IN_DIM    1260
#define HDIM      40
#define NREAL     120       // packed gate cols: i(40) g(40) o(40); f gate dropped (c0 == 0)
#define NCOL      128
#define TILE_B    128
#define KT        36        // 1260 = 35 * 36
#define NTILES    (IN_DIM / KT)
#define NTHREADS  256
#define XS_STRIDE 40        // padded, 160B rows (16B aligned)
#define STAGE_F   (TILE_B * XS_STRIDE + KT * NCOL)   // 9728 floats = 38912 B per stage

// Packed/transposed layer-0 weight: g_Wt[k][j] = W_ih0[colmap(j)][k], j<120; 0 otherwise.
__device__ float g_Wt[IN_DIM * NCOL];

__global__ void prep_kernel(const float* __restrict__ W_ih0) {
    int idx = blockIdx.x * blockDim.x + threadIdx.x;
    if (idx >= IN_DIM * NCOL) return;
    int k = idx / NCOL;
    int j = idx - k * NCOL;
    float v = 0.0f;
    if (j < NREAL) {
        int r = (j < HDIM) ? j : j + HDIM;
        v = W_ih0[r * IN_DIM + k];
    }
    g_Wt[idx] = v;
}

__device__ __forceinline__ float sigmoidf_(float v) {
    return 1.0f / (1.0f + __expf(-v));
}
__device__ __forceinline__ unsigned long long pack2(float lo, float hi) {
    unsigned long long r;
    asm("mov.b64 %0, {%1, %2};" : "=l"(r) : "f"(lo), "f"(hi));
    return r;
}
__device__ __forceinline__ void unpack2(unsigned long long v, float& lo, float& hi) {
    asm("mov.b64 {%0, %1}, %2;" : "=f"(lo), "=f"(hi) : "l"(v));
}
__device__ __forceinline__ void fma2(unsigned long long& d, unsigned long long a, unsigned long long b) {
    asm("fma.rn.f32x2 %0, %1, %2, %0;" : "+l"(d) : "l"(a), "l"(b));
}
__device__ __forceinline__ void cp_async16(uint32_t dst, const void* src) {
    asm volatile("cp.async.cg.shared.global [%0], [%1], 16;" :: "r"(dst), "l"(src));
}
__device__ __forceinline__ void cp_commit() {
    asm volatile("cp.async.commit_group;" ::: "memory");
}
template <int N>
__device__ __forceinline__ void cp_wait() {
    asm volatile("cp.async.wait_group %0;" :: "n"(N) : "memory");
}

// Small LSTM layer (K = 40), n-major map: weight row uniform per warp.
__device__ __forceinline__ void small_lstm_layer(
    const float* __restrict__ hin, float* __restrict__ hout,
    const float* __restrict__ W, const float* __restrict__ bi,
    const float* __restrict__ bh, int tid)
{
    #pragma unroll
    for (int l = 0; l < (TILE_B * HDIM) / NTHREADS; l++) {
        int idx = tid + l * NTHREADS;
        int n = idx / TILE_B;               // uniform across warp
        int r = idx - n * TILE_B;           // lane-consecutive
        float si = bi[n] + bh[n];
        float sg = bi[2 * HDIM + n] + bh[2 * HDIM + n];
        float so = bi[3 * HDIM + n] + bh[3 * HDIM + n];
        const float4* hv = reinterpret_cast<const float4*>(&hin[r * HDIM]);
        const float4* wi = reinterpret_cast<const float4*>(&W[n * HDIM]);
        const float4* wg = reinterpret_cast<const float4*>(&W[(2 * HDIM + n) * HDIM]);
        const float4* wo = reinterpret_cast<const float4*>(&W[(3 * HDIM + n) * HDIM]);
        #pragma unroll
        for (int q = 0; q < HDIM / 4; q++) {
            float4 h4 = hv[q];
            float4 a = wi[q];
            float4 b = wg[q];
            float4 c = wo[q];
            si += h4.x * a.x + h4.y * a.y + h4.z * a.z + h4.w * a.w;
            sg += h4.x * b.x + h4.y * b.y + h4.z * b.z + h4.w * b.w;
            so += h4.x * c.x + h4.y * c.y + h4.z * c.z + h4.w * c.w;
        }
        float cc = sigmoidf_(si) * tanhf(sg);
        hout[r * HDIM + n] = sigmoidf_(so) * tanhf(cc);
    }
}

__global__ __launch_bounds__(NTHREADS, 2) void lstm_kernel(
    const float* __restrict__ x,
    const float* __restrict__ b_ih0, const float* __restrict__ b_hh0,
    const float* __restrict__ W1, const float* __restrict__ b_ih1, const float* __restrict__ b_hh1,
    const float* __restrict__ W2, const float* __restrict__ b_ih2, const float* __restrict__ b_hh2,
    const float* __restrict__ Wout, const float* __restrict__ b_out,
    float* __restrict__ out)
{
    // 77824 B dynamic smem: two pipeline stages of (Xs[128][40] | Ws[36][128]).
    // Epilogue aliases: Gs[128][128] (64KB), then hA/hB (2 x 20KB).
    extern __shared__ float smem[];

    const int tid = threadIdx.x;
    const int tx = tid & 15;
    const int ty = tid >> 4;
    const int c0 = tx * 8;
    const long long bbase = (long long)blockIdx.x * TILE_B;
    const float* xblk = x + bbase * IN_DIM;

    // ---- cp.async tile loader: X (128x36 f32) + W (36x128 f32) into stage s ----
    auto load_tile = [&](int s, int kt) {
        float* Xs = smem + s * STAGE_F;
        float* Ws = Xs + TILE_B * XS_STRIDE;
        #pragma unroll
        for (int l = 0; l < 5; l++) {
            int idx = tid + l * NTHREADS;               // < 1280, need < 1152
            if (idx < (TILE_B * KT) / 4) {
                int row = idx / (KT / 4);
                int q = idx - row * (KT / 4);
                uint32_t dst = (uint32_t)__cvta_generic_to_shared(&Xs[row * XS_STRIDE + 4 * q]);
                cp_async16(dst, &xblk[row * IN_DIM + kt + 4 * q]);
            }
        }
        #pragma unroll
        for (int l = 0; l < 5; l++) {
            int idx = tid + l * NTHREADS;
            if (idx < (KT * NCOL) / 4) {
                uint32_t dst = (uint32_t)__cvta_generic_to_shared(&Ws[4 * idx]);
                cp_async16(dst, &g_Wt[kt * NCOL + 4 * idx]);
            }
        }
    };

    // Accumulators: 8 rows x 4 packed col-pairs, init with gate bias
    unsigned long long acc[8][4];
    {
        float bias[8];
        #pragma unroll
        for (int jj = 0; jj < 8; jj++) {
            int j = c0 + jj;
            float bv = 0.0f;
            if (j < NREAL) {
                int r = (j < HDIM) ? j : j + HDIM;
                bv = b_ih0[r] + b_hh0[r];
            }
            bias[jj] = bv;
        }
        #pragma unroll
        for (int q = 0; q < 4; q++) {
            unsigned long long p = pack2(bias[2 * q], bias[2 * q + 1]);
            #pragma unroll
            for (int i = 0; i < 8; i++) acc[i][q] = p;
        }
    }

    // ---- pipelined k-loop ----
    load_tile(0, 0);
    cp_commit();

    for (int t = 0; t < NTILES; t++) {
        if (t + 1 < NTILES) {
            load_tile((t + 1) & 1, (t + 1) * KT);
            cp_commit();
            cp_wait<1>();
        } else {
            cp_wait<0>();
        }
        __syncthreads();

        const float* Xs = smem + (t & 1) * STAGE_F;
        const float* Ws = Xs + TILE_B * XS_STRIDE;

        #pragma unroll
        for (int k4 = 0; k4 < KT / 4; k4++) {
            // 1 LDS.128 per row per 4 k-steps
            float4 xv[8];
            #pragma unroll
            for (int i = 0; i < 8; i++)
                xv[i] = *reinterpret_cast<const float4*>(&Xs[(ty + 16 * i) * XS_STRIDE + 4 * k4]);
            #pragma unroll
            for (int kk = 0; kk < 4; kk++) {
                ulonglong2 w0 = *reinterpret_cast<const ulonglong2*>(&Ws[(4 * k4 + kk) * NCOL + c0]);
                ulonglong2 w1 = *reinterpret_cast<const ulonglong2*>(&Ws[(4 * k4 + kk) * NCOL + c0 + 4]);
                #pragma unroll
                for (int i = 0; i < 8; i++) {
                    float av = (kk == 0) ? xv[i].x : (kk == 1) ? xv[i].y : (kk == 2) ? xv[i].z : xv[i].w;
                    unsigned long long a2 = pack2(av, av);
                    fma2(acc[i][0], a2, w0.x);
                    fma2(acc[i][1], a2, w0.y);
                    fma2(acc[i][2], a2, w1.x);
                    fma2(acc[i][3], a2, w1.y);
                }
            }
        }
        __syncthreads();
    }

    // ---- epilogue ----
    float* Gs = smem;                       // [128][128] gate pre-activations

    #pragma unroll
    for (int i = 0; i < 8; i++) {
        int r = ty + 16 * i;
        float v[8];
        #pragma unroll
        for (int q = 0; q < 4; q++) unpack2(acc[i][q], v[2 * q], v[2 * q + 1]);
        float4* dst = reinterpret_cast<float4*>(&Gs[r * NCOL + c0]);
        dst[0] = make_float4(v[0], v[1], v[2], v[3]);
        dst[1] = make_float4(v[4], v[5], v[6], v[7]);
    }
    __syncthreads();

    // layer-0 activations, held in regs across the re-aliasing sync
    float hreg[(TILE_B * HDIM) / NTHREADS];
    #pragma unroll
    for (int l = 0; l < (TILE_B * HDIM) / NTHREADS; l++) {
        int idx = tid + l * NTHREADS;
        int r = idx / HDIM;
        int n = idx - r * HDIM;
        float gi = Gs[r * NCOL + n];
        float gg = Gs[r * NCOL + HDIM + n];
        float go = Gs[r * NCOL + 2 * HDIM + n];
        float cc = sigmoidf_(gi) * tanhf(gg);
        hreg[l] = sigmoidf_(go) * tanhf(cc);
    }
    __syncthreads();

    float* hA = smem;                             // [128][40]
    float* hB = smem + TILE_B * HDIM;             // [128][40]
    #pragma unroll
    for (int l = 0; l < (TILE_B * HDIM) / NTHREADS; l++) {
        int idx = tid + l * NTHREADS;
        hA[idx] = hreg[l];
    }
    __syncthreads();

    small_lstm_layer(hA, hB, W1, b_ih1, b_hh1, tid);
    __syncthreads();
    small_lstm_layer(hB, hA, W2, b_ih2, b_hh2, tid);
    __syncthreads();

    // output head: 128 rows x 4 outputs, o uniform per warp
    #pragma unroll
    for (int l = 0; l < (TILE_B * 4) / NTHREADS; l++) {
        int idx = tid + l * NTHREADS;
        int o = idx / TILE_B;               // uniform across warp
        int r = idx - o * TILE_B;           // lane-consecutive
        const float4* hv = reinterpret_cast<const float4*>(&hA[r * HDIM]);
        const float4* wv = reinterpret_cast<const float4*>(&Wout[o * HDIM]);
        float s = b_out[o];
        #pragma unroll
        for (int q = 0; q < HDIM / 4; q++) {
            float4 h4 = hv[q];
            float4 w4 = wv[q];
            s += h4.x * w4.x + h4.y * w4.y + h4.z * w4.z + h4.w * w4.w;
        }
        out[(bbase + r) * 4 + o] = s;
    }
}

extern "C" void kernel_launch(void* const* d_in, const int* in_sizes, int n_in,
                              void* d_out, int out_size) {
    const float* x     = (const float*)d_in[0];
    const float* W_ih0 = (const float*)d_in[1];
    const float* b_ih0 = (const float*)d_in[3];
    const float* b_hh0 = (const float*)d_in[4];
    const float* W_ih1 = (const float*)d_in[5];
    const float* b_ih1 = (const float*)d_in[7];
    const float* b_hh1 = (const float*)d_in[8];
    const float* W_ih2 = (const float*)d_in[9];
    const float* b_ih2 = (const float*)d_in[11];
    const float* b_hh2 = (const float*)d_in[12];
    const float* W_out = (const float*)d_in[13];
    const float* b_out = (const float*)d_in[14];
    float* out = (float*)d_out;

    cudaFuncSetAttribute(lstm_kernel,
                         cudaFuncAttributeMaxDynamicSharedMemorySize,
                         2 * STAGE_F * (int)sizeof(float));

    prep_kernel<<<(IN_DIM * NCOL + 255) / 256, 256>>>(W_ih0);
    lstm_kernel<<<B_TOTAL / TILE_B, NTHREADS, 2 * STAGE_F * sizeof(float)>>>(
        x, b_ih0, b_hh0,
        W_ih1, b_ih1, b_hh1,
        W_ih2, b_ih2, b_hh2,
        W_out, b_out, out);
}

// round 5
// speedup vs baseline: 3.0847x; 1.9533x over previous
#include <cuda_runtime.h>
#include <cuda_bf16.h>
#include <cstdint>

// Problem constants
#define B_TOTAL   65536
#define IN_DIM    1260
#define HDIM      40
#define TILE_B    128
#define KTILE     32          // K tile (f32 elems); padded K = 1280
#define NT        40          // 1280 / 32
#define NTHREADS  256
#define XSTR      40          // f32 stride of x tile rows (160B: 16B-aligned, LDS.64 conflict-free)
#define GS_STRIDE 124

#define X_STAGE_BYTES (TILE_B * XSTR * 4)              // 20480
#define W_STAGE_BYTES 16384                            // hi 8KB | lo 8KB
#define STAGE_BYTES   (X_STAGE_BYTES + W_STAGE_BYTES)  // 36864
#define SMEM_BYTES    (2 * STAGE_BYTES)                // 73728

// Pre-packed W (layer 0): per K-tile, [128 n][32 k] bf16 SW64-swizzled, hi then lo.
// Packed gate cols: i(0-39) g(40-79) o(80-119); f gate dropped (c0 == 0). n>=120, k>=1260 zero.
__device__ __align__(16) unsigned char g_Wpk[NT * 16384];

__global__ void prep_pack(const float* __restrict__ W_ih0) {
    int idx = blockIdx.x * blockDim.x + threadIdx.x;
    if (idx >= NT * 128 * KTILE) return;
    int t = idx / (128 * KTILE);
    int rem = idx - t * (128 * KTILE);
    int n = rem / KTILE;
    int k = rem - n * KTILE;
    int gk = t * KTILE + k;
    float v = 0.0f;
    if (n < 120 && gk < IN_DIM) {
        int r = (n < HDIM) ? n : n + HDIM;
        v = W_ih0[r * IN_DIM + gk];
    }
    __nv_bfloat16 hi = __float2bfloat16_rn(v);
    float lo = v - __bfloat162float(hi);
    __nv_bfloat16 lob = __float2bfloat16_rn(lo);
    uint32_t off = (uint32_t)(n * 64 + 2 * k);
    off ^= (off >> 3) & 0x30;                 // SW64 swizzle (64B rows)
    *reinterpret_cast<uint16_t*>(g_Wpk + t * 16384 + off) = *reinterpret_cast<uint16_t*>(&hi);
    *reinterpret_cast<uint16_t*>(g_Wpk + t * 16384 + 8192 + off) = *reinterpret_cast<uint16_t*>(&lob);
}

// ---------------- helpers ----------------
__device__ __forceinline__ uint32_t smem_u32(const void* p) {
    uint32_t a;
    asm("{ .reg .u64 t; cvta.to.shared.u64 t, %1; cvt.u32.u64 %0, t; }" : "=r"(a) : "l"(p));
    return a;
}
__device__ __forceinline__ float sigmoidf_(float v) { return 1.0f / (1.0f + __expf(-v)); }

__device__ __forceinline__ void cp_async16(uint32_t dst, const void* src) {
    asm volatile("cp.async.cg.shared.global [%0], [%1], 16;" :: "r"(dst), "l"(src));
}
__device__ __forceinline__ void cp_commit() { asm volatile("cp.async.commit_group;" ::: "memory"); }
template <int N>
__device__ __forceinline__ void cp_wait() {
    asm volatile("cp.async.wait_group %0;" :: "n"(N) : "memory");
}

__device__ __forceinline__ void ldsm4(uint32_t* r, uint32_t addr) {
    asm volatile("ldmatrix.sync.aligned.m8n8.x4.shared.b16 {%0,%1,%2,%3}, [%4];"
                 : "=r"(r[0]), "=r"(r[1]), "=r"(r[2]), "=r"(r[3]) : "r"(addr));
}
__device__ __forceinline__ void ldsm2(uint32_t* r, uint32_t addr) {
    asm volatile("ldmatrix.sync.aligned.m8n8.x2.shared.b16 {%0,%1}, [%2];"
                 : "=r"(r[0]), "=r"(r[1]) : "r"(addr));
}
__device__ __forceinline__ void mma16816(float* c, const uint32_t* a, uint32_t b0, uint32_t b1) {
    asm volatile("mma.sync.aligned.m16n8k16.row.col.f32.bf16.bf16.f32 "
                 "{%0,%1,%2,%3}, {%4,%5,%6,%7}, {%8,%9}, {%0,%1,%2,%3};"
                 : "+f"(c[0]), "+f"(c[1]), "+f"(c[2]), "+f"(c[3])
                 : "r"(a[0]), "r"(a[1]), "r"(a[2]), "r"(a[3]), "r"(b0), "r"(b1));
}
// f32 pair -> bf16x2 hi + bf16x2 lo (split precision)
__device__ __forceinline__ void split2(float2 v, uint32_t& hi, uint32_t& lo) {
    __nv_bfloat162 h = __floats2bfloat162_rn(v.x, v.y);
    float2 hf = __bfloat1622float2(h);
    __nv_bfloat162 l = __floats2bfloat162_rn(v.x - hf.x, v.y - hf.y);
    hi = *reinterpret_cast<uint32_t*>(&h);
    lo = *reinterpret_cast<uint32_t*>(&l);
}

// Small LSTM layer (K = 40), n-major map: weight row uniform per warp.
__device__ __forceinline__ void small_lstm_layer(
    const float* __restrict__ hin, float* __restrict__ hout,
    const float* __restrict__ W, const float* __restrict__ bi,
    const float* __restrict__ bh, int tid)
{
    #pragma unroll
    for (int l = 0; l < (TILE_B * HDIM) / NTHREADS; l++) {
        int idx = tid + l * NTHREADS;
        int n = idx / TILE_B;               // uniform across warp
        int r = idx - n * TILE_B;           // lane-consecutive
        float si = bi[n] + bh[n];
        float sg = bi[2 * HDIM + n] + bh[2 * HDIM + n];
        float so = bi[3 * HDIM + n] + bh[3 * HDIM + n];
        const float4* hv = reinterpret_cast<const float4*>(&hin[r * HDIM]);
        const float4* wi = reinterpret_cast<const float4*>(&W[n * HDIM]);
        const float4* wg = reinterpret_cast<const float4*>(&W[(2 * HDIM + n) * HDIM]);
        const float4* wo = reinterpret_cast<const float4*>(&W[(3 * HDIM + n) * HDIM]);
        #pragma unroll
        for (int q = 0; q < HDIM / 4; q++) {
            float4 h4 = hv[q];
            float4 a = wi[q];
            float4 b = wg[q];
            float4 c = wo[q];
            si += h4.x * a.x + h4.y * a.y + h4.z * a.z + h4.w * a.w;
            sg += h4.x * b.x + h4.y * b.y + h4.z * b.z + h4.w * b.w;
            so += h4.x * c.x + h4.y * c.y + h4.z * c.z + h4.w * c.w;
        }
        float cc = sigmoidf_(si) * tanhf(sg);
        hout[r * HDIM + n] = sigmoidf_(so) * tanhf(cc);
    }
}

__global__ __launch_bounds__(NTHREADS, 2) void lstm_kernel(
    const float* __restrict__ x,
    const float* __restrict__ b_ih0, const float* __restrict__ b_hh0,
    const float* __restrict__ W1, const float* __restrict__ b_ih1, const float* __restrict__ b_hh1,
    const float* __restrict__ W2, const float* __restrict__ b_ih2, const float* __restrict__ b_hh2,
    const float* __restrict__ Wout, const float* __restrict__ b_out,
    float* __restrict__ out)
{
    extern __shared__ __align__(16) unsigned char smem_c[];
    float* smem_f = reinterpret_cast<float*>(smem_c);
    const uint32_t sbase = smem_u32(smem_c);

    const int tid = threadIdx.x;
    const int wid = tid >> 5;
    const int lid = tid & 31;
    const long long bbase = (long long)blockIdx.x * TILE_B;
    const float* xblk = x + bbase * IN_DIM;

    // Accumulators: 15 n8-tiles x m16n8 frag (4 f32) per warp
    float acc[15][4];
    #pragma unroll
    for (int i = 0; i < 15; i++) {
        acc[i][0] = 0.f; acc[i][1] = 0.f; acc[i][2] = 0.f; acc[i][3] = 0.f;
    }

    // cp.async tile loader: x raw f32 (128x32, stride 40) + prepacked W (16KB)
    auto load_tile = [&](int s, int t) {
        const int kt = t * KTILE;
        uint32_t xs = sbase + s * STAGE_BYTES;
        uint32_t ws = xs + X_STAGE_BYTES;
        #pragma unroll
        for (int i = 0; i < 4; i++) {
            int idx = tid + i * NTHREADS;       // < 1024
            int row = idx >> 3;
            int c = idx & 7;
            uint32_t dst = xs + row * (XSTR * 4) + c * 16;
            if (kt + 4 * c <= IN_DIM - 4) {
                cp_async16(dst, &xblk[row * IN_DIM + kt + 4 * c]);
            } else {
                asm volatile("st.shared.v4.b32 [%0], {%1,%1,%1,%1};" :: "r"(dst), "r"(0u) : "memory");
            }
        }
        #pragma unroll
        for (int i = 0; i < 4; i++) {
            int idx = tid + i * NTHREADS;       // < 1024
            cp_async16(ws + idx * 16, g_Wpk + t * 16384 + idx * 16);
        }
    };

    load_tile(0, 0);
    cp_commit();

    const int gr = (wid << 4) + (lid >> 2);   // A rows gr, gr+8
    const int kc = (lid & 3) * 2;
    const int lg = lid & 7;                   // ldmatrix lane row
    const int ch = (lid >> 3) & 1;            // 16B k-chunk
    const int nhalf = (lid >> 4) & 1;         // +8 n for matrices 2,3

    for (int t = 0; t < NT; t++) {
        if (t + 1 < NT) { load_tile((t + 1) & 1, t + 1); cp_commit(); cp_wait<1>(); }
        else cp_wait<0>();
        __syncthreads();

        const int s = t & 1;
        const float* xs_f = smem_f + s * (STAGE_BYTES / 4);
        const uint32_t wbase = sbase + s * STAGE_BYTES + X_STAGE_BYTES;

        #pragma unroll
        for (int ks = 0; ks < 2; ks++) {
            // A fragments from f32 smem (conflict-free LDS.64), split to bf16 hi/lo
            uint32_t ahi[4], alo[4];
            {
                float2 v0 = *reinterpret_cast<const float2*>(&xs_f[gr * XSTR + ks * 16 + kc]);
                float2 v1 = *reinterpret_cast<const float2*>(&xs_f[(gr + 8) * XSTR + ks * 16 + kc]);
                float2 v2 = *reinterpret_cast<const float2*>(&xs_f[gr * XSTR + ks * 16 + kc + 8]);
                float2 v3 = *reinterpret_cast<const float2*>(&xs_f[(gr + 8) * XSTR + ks * 16 + kc + 8]);
                split2(v0, ahi[0], alo[0]);
                split2(v1, ahi[1], alo[1]);
                split2(v2, ahi[2], alo[2]);
                split2(v3, ahi[3], alo[3]);
            }
            // W_hi pass: hi*Whi + lo*Whi
            #pragma unroll
            for (int g = 0; g < 7; g++) {
                int n_l = 16 * g + 8 * nhalf + lg;
                uint32_t off = (uint32_t)(n_l * 64 + ks * 32 + ch * 16);
                off ^= (off >> 3) & 0x30;
                uint32_t b[4];
                ldsm4(b, wbase + off);
                mma16816(acc[2 * g],     ahi, b[0], b[1]);
                mma16816(acc[2 * g],     alo, b[0], b[1]);
                mma16816(acc[2 * g + 1], ahi, b[2], b[3]);
                mma16816(acc[2 * g + 1], alo, b[2], b[3]);
            }
            {   // tail n-tile 14 (n 112-119), x2
                int n_l = 112 + lg;
                uint32_t off = (uint32_t)(n_l * 64 + ks * 32 + ch * 16);
                off ^= (off >> 3) & 0x30;
                uint32_t b[2];
                ldsm2(b, wbase + off);
                mma16816(acc[14], ahi, b[0], b[1]);
                mma16816(acc[14], alo, b[0], b[1]);
            }
            // W_lo pass: hi*Wlo
            #pragma unroll
            for (int g = 0; g < 7; g++) {
                int n_l = 16 * g + 8 * nhalf + lg;
                uint32_t off = (uint32_t)(n_l * 64 + ks * 32 + ch * 16);
                off ^= (off >> 3) & 0x30;
                uint32_t b[4];
                ldsm4(b, wbase + 8192 + off);
                mma16816(acc[2 * g],     ahi, b[0], b[1]);
                mma16816(acc[2 * g + 1], ahi, b[2], b[3]);
            }
            {
                int n_l = 112 + lg;
                uint32_t off = (uint32_t)(n_l * 64 + ks * 32 + ch * 16);
                off ^= (off >> 3) & 0x30;
                uint32_t b[2];
                ldsm2(b, wbase + 8192 + off);
                mma16816(acc[14], ahi, b[0], b[1]);
            }
        }
        __syncthreads();
    }

    // ---- epilogue: frags -> Gs smem ----
    float* Gs = smem_f;                       // [128][124]
    {
        int r0 = (wid << 4) + (lid >> 2);
        int cbase = (lid & 3) * 2;
        #pragma unroll
        for (int nt = 0; nt < 15; nt++) {
            int col = nt * 8 + cbase;
            *reinterpret_cast<float2*>(&Gs[r0 * GS_STRIDE + col]) = make_float2(acc[nt][0], acc[nt][1]);
            *reinterpret_cast<float2*>(&Gs[(r0 + 8) * GS_STRIDE + col]) = make_float2(acc[nt][2], acc[nt][3]);
        }
    }
    __syncthreads();

    // layer-0 activations (+ gate biases), held in regs across re-aliasing sync
    float hreg[(TILE_B * HDIM) / NTHREADS];
    #pragma unroll
    for (int l = 0; l < (TILE_B * HDIM) / NTHREADS; l++) {
        int idx = tid + l * NTHREADS;
        int r = idx / HDIM;
        int n = idx - r * HDIM;
        float gi = Gs[r * GS_STRIDE + n]            + b_ih0[n] + b_hh0[n];
        float gg = Gs[r * GS_STRIDE + HDIM + n]     + b_ih0[2 * HDIM + n] + b_hh0[2 * HDIM + n];
        float go = Gs[r * GS_STRIDE + 2 * HDIM + n] + b_ih0[3 * HDIM + n] + b_hh0[3 * HDIM + n];
        float cc = sigmoidf_(gi) * tanhf(gg);
        hreg[l] = sigmoidf_(go) * tanhf(cc);
    }
    __syncthreads();

    float* hA = smem_f;                            // [128][40]
    float* hB = smem_f + TILE_B * HDIM;            // [128][40]
    #pragma unroll
    for (int l = 0; l < (TILE_B * HDIM) / NTHREADS; l++)
        hA[tid + l * NTHREADS] = hreg[l];
    __syncthreads();

    small_lstm_layer(hA, hB, W1, b_ih1, b_hh1, tid);
    __syncthreads();
    small_lstm_layer(hB, hA, W2, b_ih2, b_hh2, tid);
    __syncthreads();

    // output head: 128 rows x 4 outputs, o uniform per warp
    #pragma unroll
    for (int l = 0; l < (TILE_B * 4) / NTHREADS; l++) {
        int idx = tid + l * NTHREADS;
        int o = idx / TILE_B;
        int r = idx - o * TILE_B;
        const float4* hv = reinterpret_cast<const float4*>(&hA[r * HDIM]);
        const float4* wv = reinterpret_cast<const float4*>(&Wout[o * HDIM]);
        float s = b_out[o];
        #pragma unroll
        for (int q = 0; q < HDIM / 4; q++) {
            float4 h4 = hv[q];
            float4 w4 = wv[q];
            s += h4.x * w4.x + h4.y * w4.y + h4.z * w4.z + h4.w * w4.w;
        }
        out[(bbase + r) * 4 + o] = s;
    }
}

extern "C" void kernel_launch(void* const* d_in, const int* in_sizes, int n_in,
                              void* d_out, int out_size) {
    const float* x     = (const float*)d_in[0];
    const float* W_ih0 = (const float*)d_in[1];
    const float* b_ih0 = (const float*)d_in[3];
    const float* b_hh0 = (const float*)d_in[4];
    const float* W_ih1 = (const float*)d_in[5];
    const float* b_ih1 = (const float*)d_in[7];
    const float* b_hh1 = (const float*)d_in[8];
    const float* W_ih2 = (const float*)d_in[9];
    const float* b_ih2 = (const float*)d_in[11];
    const float* b_hh2 = (const float*)d_in[12];
    const float* W_out = (const float*)d_in[13];
    const float* b_out = (const float*)d_in[14];
    float* out = (float*)d_out;

    static int attr_set = 0;
    if (!attr_set) {
        cudaFuncSetAttribute(lstm_kernel,
                             cudaFuncAttributeMaxDynamicSharedMemorySize, SMEM_BYTES);
        attr_set = 1;
    }

    prep_pack<<<(NT * 128 * KTILE + 255) / 256, 256>>>(W_ih0);
    lstm_kernel<<<B_TOTAL / TILE_B, NTHREADS, SMEM_BYTES>>>(
        x, b_ih0, b_hh0,
        W_ih1, b_ih1, b_hh1,
        W_ih2, b_ih2, b_hh2,
        W_out, b_out, out);
}